// round 5
// baseline (speedup 1.0000x reference)
#include <cuda_runtime.h>
#include <cuda_bf16.h>
#include <cstdint>
#include <math.h>

// Problem dims
constexpr int B_ = 4, T_ = 2048, DM_ = 1024, H_ = 16, D_ = 64;
constexpr int NROWS = B_ * T_;           // 8192
constexpr int KP = 3072;                 // 3-term split: [ah|al|ah] . [bh|bh|bl]
constexpr int STATE_ELEMS = B_ * H_ * D_ * D_;

// ---------------- scratch (device globals; allocation-free) ----------------
__device__ float g_QKV[(size_t)NROWS * 3072];   // fused Q|K|V fp32
__device__ float g_Y[(size_t)NROWS * DM_];
__device__ float g_alpha[NROWS * H_];
__device__ float g_beta[NROWS * H_];
__device__ float g_Sdump[STATE_ELEMS];
__device__ float g_Wab32[32 * DM_];
__device__ __nv_bfloat16 g_A2[(size_t)NROWS * KP];
__device__ __nv_bfloat16 g_Y2[(size_t)NROWS * KP];
__device__ __nv_bfloat16 g_Wqkv[(size_t)3072 * KP];   // rows: Wq|Wk|Wv cols
__device__ __nv_bfloat16 g_Wto[(size_t)DM_ * KP];

// ---------------------------------------------------------------------------
// bf16 mma.sync GEMM: C[8192, N] = A'[8192,3072] @ B'[N,3072]^T
// CTA 128x128, 8 warps (2M x 4N), warp tile 64x32, Kc=32, 4-stage cp.async
// pipeline, 2 CTAs/SM. smem rows padded to 40 halves (80B), conflict-free.
// ---------------------------------------------------------------------------
__global__ __launch_bounds__(256, 2) void gemm_mma(const __nv_bfloat16* __restrict__ A,
                                                   const __nv_bfloat16* __restrict__ Bw,
                                                   float* __restrict__ C, int ldc) {
    extern __shared__ char sm[];
    const int tid = threadIdx.x;
    const int lane = tid & 31, wid = tid >> 5;
    const int wm = wid & 1, wn = wid >> 1;       // 2 x 4 warp grid
    const int row0 = blockIdx.y * 128;
    const int col0 = blockIdx.x * 128;

    uint32_t sb;
    asm("{ .reg .u64 t; cvta.to.shared.u64 t, %1; cvt.u32.u64 %0, t; }" : "=r"(sb) : "l"(sm));

    // stage = A(128*80B = 10240) + B(10240) = 20480 bytes; 4 stages.
    constexpr uint32_t STG = 20480u;

    float acc[4][4][4];
#pragma unroll
    for (int i = 0; i < 4; ++i)
#pragma unroll
        for (int j = 0; j < 4; ++j)
#pragma unroll
            for (int q = 0; q < 4; ++q) acc[i][j][q] = 0.f;

    auto load_chunk = [&](int c, int stg) {
        const __nv_bfloat16* gA = A + (size_t)row0 * KP + c * 32;
        uint32_t ab = sb + (uint32_t)stg * STG;
#pragma unroll
        for (int l = 0; l < 2; ++l) {
            int idx = tid + (l << 8);
            int r = idx >> 2, s = idx & 3;
            uint32_t so = ab + (uint32_t)(r * 80 + s * 16);
            const void* gp = gA + (size_t)r * KP + s * 8;
            asm volatile("cp.async.cg.shared.global [%0], [%1], 16;" :: "r"(so), "l"(gp));
        }
        const __nv_bfloat16* gB = Bw + (size_t)col0 * KP + c * 32;
        uint32_t bbx = sb + (uint32_t)stg * STG + 10240u;
#pragma unroll
        for (int l = 0; l < 2; ++l) {
            int idx = tid + (l << 8);
            int n = idx >> 2, s = idx & 3;
            uint32_t so = bbx + (uint32_t)(n * 80 + s * 16);
            const void* gp = gB + (size_t)n * KP + s * 8;
            asm volatile("cp.async.cg.shared.global [%0], [%1], 16;" :: "r"(so), "l"(gp));
        }
        asm volatile("cp.async.commit_group;" ::: "memory");
    };

    // per-lane ldmatrix base offsets (halves); pad-40 layout proven in R3
    const uint32_t a_base = (uint32_t)((wm * 64 + (lane & 15)) * 40 + ((lane >> 4) << 3));
    const uint32_t b_base = (uint32_t)((wn * 32 + (((lane >> 4) & 1) << 3) + (lane & 7)) * 40 +
                                       (((lane >> 3) & 1) << 3));

    load_chunk(0, 0);
    load_chunk(1, 1);
    load_chunk(2, 2);

    constexpr int NCH = KP / 32;  // 96
    for (int c = 0; c < NCH; ++c) {
        asm volatile("cp.async.wait_group 2;" ::: "memory");   // stage c landed
        __syncthreads();                                       // readers of stage (c-1)&3 done
        if (c + 3 < NCH)
            load_chunk(c + 3, (c + 3) & 3);
        else
            asm volatile("cp.async.commit_group;" ::: "memory");  // keep group count in step

        const uint32_t ab = sb + (uint32_t)(c & 3) * STG;
        const uint32_t bbs = ab + 10240u;
#pragma unroll
        for (int ks = 0; ks < 2; ++ks) {
            uint32_t af[4][4];
#pragma unroll
            for (int mi = 0; mi < 4; ++mi) {
                uint32_t addr = ab + (a_base + (uint32_t)(mi * 16 * 40 + ks * 16)) * 2;
                asm volatile("ldmatrix.sync.aligned.m8n8.x4.shared.b16 {%0,%1,%2,%3}, [%4];"
                             : "=r"(af[mi][0]), "=r"(af[mi][1]), "=r"(af[mi][2]), "=r"(af[mi][3])
                             : "r"(addr));
            }
            uint32_t bf[4][2];
#pragma unroll
            for (int nb = 0; nb < 2; ++nb) {
                uint32_t addr = bbs + (b_base + (uint32_t)(nb * 16 * 40 + ks * 16)) * 2;
                asm volatile("ldmatrix.sync.aligned.m8n8.x4.shared.b16 {%0,%1,%2,%3}, [%4];"
                             : "=r"(bf[2 * nb][0]), "=r"(bf[2 * nb][1]),
                               "=r"(bf[2 * nb + 1][0]), "=r"(bf[2 * nb + 1][1])
                             : "r"(addr));
            }
#pragma unroll
            for (int mi = 0; mi < 4; ++mi)
#pragma unroll
                for (int ni = 0; ni < 4; ++ni) {
                    asm volatile(
                        "mma.sync.aligned.m16n8k16.row.col.f32.bf16.bf16.f32 "
                        "{%0,%1,%2,%3}, {%4,%5,%6,%7}, {%8,%9}, {%0,%1,%2,%3};"
                        : "+f"(acc[mi][ni][0]), "+f"(acc[mi][ni][1]),
                          "+f"(acc[mi][ni][2]), "+f"(acc[mi][ni][3])
                        : "r"(af[mi][0]), "r"(af[mi][1]), "r"(af[mi][2]), "r"(af[mi][3]),
                          "r"(bf[ni][0]), "r"(bf[ni][1]));
                }
        }
    }

    const int rb = row0 + wm * 64 + (lane >> 2);
    const int cb = col0 + wn * 32 + (lane & 3) * 2;
#pragma unroll
    for (int mi = 0; mi < 4; ++mi)
#pragma unroll
        for (int ni = 0; ni < 4; ++ni) {
            int r = rb + mi * 16, cc = cb + ni * 8;
            *(float2*)(C + (size_t)r * ldc + cc) = make_float2(acc[mi][ni][0], acc[mi][ni][1]);
            *(float2*)(C + (size_t)(r + 8) * ldc + cc) =
                make_float2(acc[mi][ni][2], acc[mi][ni][3]);
        }
}

// ---------------------------------------------------------------------------
// fp32 -> 3-term split bf16: out[m] = [hi(1024) | lo(1024) | hi(1024)]
// ---------------------------------------------------------------------------
__global__ __launch_bounds__(256) void convert_split3(const float* __restrict__ in,
                                                      __nv_bfloat16* __restrict__ out) {
    size_t i = (size_t)blockIdx.x * 256 + threadIdx.x;   // float4 group id
    float4 v = ((const float4*)in)[i];
    size_t m = i >> 8;
    int k4 = (int)(i & 255) << 2;
    __nv_bfloat16 h0 = __float2bfloat16(v.x), h1 = __float2bfloat16(v.y);
    __nv_bfloat16 h2 = __float2bfloat16(v.z), h3 = __float2bfloat16(v.w);
    __nv_bfloat16 l0 = __float2bfloat16(v.x - __bfloat162float(h0));
    __nv_bfloat16 l1 = __float2bfloat16(v.y - __bfloat162float(h1));
    __nv_bfloat16 l2 = __float2bfloat16(v.z - __bfloat162float(h2));
    __nv_bfloat16 l3 = __float2bfloat16(v.w - __bfloat162float(h3));
    __nv_bfloat162 hA = __halves2bfloat162(h0, h1), hB = __halves2bfloat162(h2, h3);
    __nv_bfloat162 lA = __halves2bfloat162(l0, l1), lB = __halves2bfloat162(l2, l3);
    __nv_bfloat162* o0 = (__nv_bfloat162*)(out + m * KP + k4);
    o0[0] = hA; o0[1] = hB;
    __nv_bfloat162* o1 = (__nv_bfloat162*)(out + m * KP + 1024 + k4);
    o1[0] = lA; o1[1] = lB;
    __nv_bfloat162* o2 = (__nv_bfloat162*)(out + m * KP + 2048 + k4);
    o2[0] = hA; o2[1] = hB;
}

// W[1024][1024] fp32 -> B'[n][3072] = [hi | hi | lo]  (transposed, K-major)
__global__ __launch_bounds__(256) void transpose_split3(const float* __restrict__ W,
                                                        __nv_bfloat16* __restrict__ out) {
    __shared__ float s[32][33];
    const int tx = threadIdx.x & 31, ty = threadIdx.x >> 5;
    const int k0 = blockIdx.y << 5, n0 = blockIdx.x << 5;
#pragma unroll
    for (int r = 0; r < 32; r += 8)
        s[ty + r][tx] = W[(size_t)(k0 + ty + r) * 1024 + n0 + tx];
    __syncthreads();
#pragma unroll
    for (int r = 0; r < 32; r += 8) {
        const int n = n0 + ty + r, k = k0 + tx;
        float v = s[tx][ty + r];
        __nv_bfloat16 h = __float2bfloat16(v);
        __nv_bfloat16 l = __float2bfloat16(v - __bfloat162float(h));
        out[(size_t)n * KP + k] = h;
        out[(size_t)n * KP + 1024 + k] = h;
        out[(size_t)n * KP + 2048 + k] = l;
    }
}

// Wa/Wb [1024][16] -> Wt32[32][1024] fp32
__global__ __launch_bounds__(256) void gates_prep32(const float* __restrict__ Wa,
                                                    const float* __restrict__ Wb,
                                                    float* __restrict__ out) {
    const int o = blockIdx.x;
    const float* W = (o < 16) ? Wa : Wb;
    const int h = o & 15;
    for (int k = threadIdx.x; k < 1024; k += 256)
        out[(size_t)o * 1024 + k] = W[k * 16 + h];
}

// ---------------------------------------------------------------------------
// Gates: logits = x @ Wt32^T, + bias, sigmoid. Block = 64 rows x 32 outputs.
// ---------------------------------------------------------------------------
__global__ __launch_bounds__(256) void gates64(const float* __restrict__ x,
                                               const float* __restrict__ Wt,
                                               const float* __restrict__ ba,
                                               const float* __restrict__ bb,
                                               float* __restrict__ alpha,
                                               float* __restrict__ beta) {
    __shared__ float xs[64][64];
    __shared__ float ws[32][65];
    const int tid = threadIdx.x;
    const int row0 = blockIdx.x * 64;
    const int rg = tid >> 5;
    const int o = tid & 31;

    float acc[8];
#pragma unroll
    for (int p = 0; p < 8; ++p) acc[p] = 0.f;

    for (int kc = 0; kc < 16; ++kc) {
        __syncthreads();
#pragma unroll
        for (int l = 0; l < 4; ++l) {
            int idx = tid + (l << 8);
            int r = idx >> 4, q = idx & 15;
            float4 v = *(const float4*)(x + (size_t)(row0 + r) * 1024 + kc * 64 + q * 4);
            *(float4*)(&xs[r][q * 4]) = v;
        }
#pragma unroll
        for (int l = 0; l < 2; ++l) {
            int idx = tid + (l << 8);
            int r = idx >> 4, q = idx & 15;
            float4 v = *(const float4*)(Wt + (size_t)r * 1024 + kc * 64 + q * 4);
            ws[r][q * 4 + 0] = v.x; ws[r][q * 4 + 1] = v.y;
            ws[r][q * 4 + 2] = v.z; ws[r][q * 4 + 3] = v.w;
        }
        __syncthreads();
#pragma unroll 8
        for (int k = 0; k < 64; ++k) {
            float wv = ws[o][k];
#pragma unroll
            for (int p = 0; p < 8; ++p)
                acc[p] = fmaf(xs[rg * 8 + p][k], wv, acc[p]);
        }
    }

    const float bias = (o < 16) ? ba[o] : bb[o - 16];
#pragma unroll
    for (int p = 0; p < 8; ++p) {
        float r = 1.f / (1.f + expf(-(acc[p] + bias)));
        int row = row0 + rg * 8 + p;
        if (o < 16) alpha[(size_t)row * 16 + o] = r;
        else        beta[(size_t)row * 16 + (o - 16)] = r;
    }
}

// ---------------------------------------------------------------------------
// K normalize over fused QKV buffer (K = cols [1024,2048))
// ---------------------------------------------------------------------------
__global__ __launch_bounds__(256) void knorm2(float* __restrict__ QKV) {
    const int w = (int)((blockIdx.x * blockDim.x + threadIdx.x) >> 5);
    const int lane = threadIdx.x & 31;
    if (w >= NROWS * H_) return;
    const int n = w >> 4, h = w & 15;
    float2* p = (float2*)(QKV + (size_t)n * 3072 + 1024 + h * 64);
    float2 v = p[lane];
    float ss = v.x * v.x + v.y * v.y;
#pragma unroll
    for (int m = 16; m; m >>= 1) ss += __shfl_xor_sync(~0u, ss, m);
    float inv = 1.f / fmaxf(sqrtf(ss), 1e-12f);
    v.x *= inv; v.y *= inv;
    p[lane] = v;
}

// ---------------------------------------------------------------------------
// Sequential scan: 128 blocks (one per (b,h,row-half)), 128 threads.
// ---------------------------------------------------------------------------
__global__ __launch_bounds__(128) void scan_kernel2(
    const float* __restrict__ QKV, const float* __restrict__ alpha,
    const float* __restrict__ beta, const float* __restrict__ S0,
    float* __restrict__ Y, float* __restrict__ Sout) {
    constexpr int CH = 16;
    __shared__ float cq[2][CH][64];
    __shared__ float ck[2][CH][64];
    __shared__ float cv[2][CH][32];
    __shared__ float ca[2][CH];
    __shared__ float cb[2][CH];

    const int tid = threadIdx.x;
    const int bh2 = blockIdx.x;          // 0..127
    const int bh = bh2 >> 1, half = bh2 & 1;
    const int b = bh >> 4, h = bh & 15;
    const int i = tid >> 2;              // row 0..31
    const int gi = half * 32 + i;        // row 0..63
    const int jg = tid & 3;
    const int j0 = jg << 4;

    float4 s4[4];
    {
        const float4* sp = (const float4*)(S0 + ((size_t)bh * 64 + gi) * 64 + j0);
        s4[0] = sp[0]; s4[1] = sp[1]; s4[2] = sp[2]; s4[3] = sp[3];
    }

    const float* rowQ = QKV + (size_t)b * T_ * 3072 + (size_t)h * 64;

    auto load_chunk = [&](int t0, int buf) {
#pragma unroll
        for (int l = 0; l < 2; ++l) {
            int idx = tid + (l << 7);
            int st = idx >> 4, f = (idx & 15) << 2;
            const float* base = rowQ + (size_t)(t0 + st) * 3072;
            *(float4*)(&cq[buf][st][f]) = *(const float4*)(base + f);
            *(float4*)(&ck[buf][st][f]) = *(const float4*)(base + 1024 + f);
        }
        {
            int st = tid >> 3, f = (tid & 7) << 2;
            const float* base = rowQ + (size_t)(t0 + st) * 3072 + 2048 + half * 32;
            *(float4*)(&cv[buf][st][f]) = *(const float4*)(base + f);
        }
        if (tid < CH)
            ca[buf][tid] = alpha[((size_t)b * T_ + t0 + tid) * H_ + h];
        else if (tid < 2 * CH)
            cb[buf][tid - CH] = beta[((size_t)b * T_ + t0 + tid - CH) * H_ + h];
    };

    const size_t ybase = (size_t)b * T_ * DM_ + (size_t)h * 64 + gi;
    const int nch = T_ / CH;
    load_chunk(0, 0);
    __syncthreads();

    for (int c = 0; c < nch; ++c) {
        const int buf = c & 1;
        if (c + 1 < nch) load_chunk((c + 1) * CH, buf ^ 1);

#pragma unroll 4
        for (int s = 0; s < CH; ++s) {
            const float a = ca[buf][s];
            const float bg = cb[buf][s];
            const float bv = bg * cv[buf][s][i];
            const float4* kp = (const float4*)(&ck[buf][s][j0]);
            const float4* qp = (const float4*)(&cq[buf][s][j0]);
            float partial = 0.f;
#pragma unroll
            for (int v = 0; v < 4; ++v) {
                float4 kk = kp[v];
                float4 qq = qp[v];
                s4[v].x = fmaf(a, s4[v].x, bv * kk.x); partial = fmaf(s4[v].x, qq.x, partial);
                s4[v].y = fmaf(a, s4[v].y, bv * kk.y); partial = fmaf(s4[v].y, qq.y, partial);
                s4[v].z = fmaf(a, s4[v].z, bv * kk.z); partial = fmaf(s4[v].z, qq.z, partial);
                s4[v].w = fmaf(a, s4[v].w, bv * kk.w); partial = fmaf(s4[v].w, qq.w, partial);
            }
            partial += __shfl_xor_sync(~0u, partial, 1);
            partial += __shfl_xor_sync(~0u, partial, 2);
            if (jg == 0)
                Y[ybase + (size_t)(c * CH + s) * DM_] = partial;
        }
        __syncthreads();
    }

    float4* so = (float4*)(Sout + ((size_t)bh * 64 + gi) * 64 + j0);
    so[0] = s4[0]; so[1] = s4[1]; so[2] = s4[2]; so[3] = s4[3];
}

// ---------------------------------------------------------------------------
extern "C" void kernel_launch(void* const* d_in, const int* in_sizes, int n_in,
                              void* d_out, int out_size) {
    (void)in_sizes; (void)n_in;
    const float* x  = (const float*)d_in[0];
    const float* S0 = (const float*)d_in[1];
    const float* Wq = (const float*)d_in[2];
    const float* Wk = (const float*)d_in[3];
    const float* Wv = (const float*)d_in[4];
    const float* Wa = (const float*)d_in[5];
    const float* ba = (const float*)d_in[6];
    const float* Wb = (const float*)d_in[7];
    const float* bb = (const float*)d_in[8];
    const float* Wo = (const float*)d_in[9];
    float* out = (float*)d_out;

    float *QKVd, *Yd, *al, *be, *Sdump, *Wab32;
    __nv_bfloat16 *A2, *Y2, *Wqkv, *Wto;
    cudaGetSymbolAddress((void**)&QKVd, g_QKV);
    cudaGetSymbolAddress((void**)&Yd, g_Y);
    cudaGetSymbolAddress((void**)&al, g_alpha);
    cudaGetSymbolAddress((void**)&be, g_beta);
    cudaGetSymbolAddress((void**)&Sdump, g_Sdump);
    cudaGetSymbolAddress((void**)&Wab32, g_Wab32);
    cudaGetSymbolAddress((void**)&A2, g_A2);
    cudaGetSymbolAddress((void**)&Y2, g_Y2);
    cudaGetSymbolAddress((void**)&Wqkv, g_Wqkv);
    cudaGetSymbolAddress((void**)&Wto, g_Wto);

    float* Sout = (out_size >= NROWS * DM_ + STATE_ELEMS) ? out + (size_t)NROWS * DM_ : Sdump;

    constexpr int GSMEM = 4 * 20480;   // 81920 per CTA (4-stage)
    cudaFuncSetAttribute(gemm_mma, cudaFuncAttributeMaxDynamicSharedMemorySize, GSMEM);

    // Launch order matters for ncu (-s 5 -c 1): QKV gemm must be launch #6.
    convert_split3<<<NROWS, 256>>>(x, A2);                               // 1
    transpose_split3<<<dim3(32, 32), 256>>>(Wq, Wqkv);                   // 2
    transpose_split3<<<dim3(32, 32), 256>>>(Wk, Wqkv + (size_t)1024 * KP); // 3
    transpose_split3<<<dim3(32, 32), 256>>>(Wv, Wqkv + (size_t)2048 * KP); // 4
    gates_prep32<<<32, 256>>>(Wa, Wb, Wab32);                            // 5
    gemm_mma<<<dim3(3072 / 128, NROWS / 128), 256, GSMEM>>>(A2, Wqkv, QKVd, 3072); // 6 <- profiled
    gates64<<<NROWS / 64, 256>>>(x, Wab32, ba, bb, al, be);              // 7
    knorm2<<<(NROWS * H_ * 32) / 256, 256>>>(QKVd);                      // 8
    scan_kernel2<<<128, 128>>>(QKVd, al, be, S0, Yd, Sout);              // 9
    convert_split3<<<NROWS, 256>>>(Yd, Y2);                              // 10
    transpose_split3<<<dim3(32, 32), 256>>>(Wo, Wto);                    // 11
    gemm_mma<<<dim3(1024 / 128, NROWS / 128), 256, GSMEM>>>(Y2, Wto, out, 1024); // 12
}

// round 7
// speedup vs baseline: 1.0449x; 1.0449x over previous
#include <cuda_runtime.h>
#include <cuda_bf16.h>
#include <cstdint>
#include <math.h>

// Problem dims
constexpr int B_ = 4, T_ = 2048, DM_ = 1024, H_ = 16, D_ = 64;
constexpr int NROWS = B_ * T_;           // 8192
constexpr int KP = 3072;                 // 3-term split: [ah|al|ah] . [bh|bh|bl]
constexpr int STATE_ELEMS = B_ * H_ * D_ * D_;

// ---------------- scratch (device globals; allocation-free) ----------------
__device__ float g_QKV[(size_t)NROWS * 3072];   // fused Q|K|V fp32
__device__ float g_Y[(size_t)NROWS * DM_];
__device__ float g_alpha[NROWS * H_];
__device__ float g_beta[NROWS * H_];
__device__ float g_Sdump[STATE_ELEMS];
__device__ float g_Wab32[32 * DM_];
__device__ __nv_bfloat16 g_A2[(size_t)NROWS * KP];
__device__ __nv_bfloat16 g_Y2[(size_t)NROWS * KP];
__device__ __nv_bfloat16 g_Wqkv[(size_t)3072 * KP];   // rows: Wq|Wk|Wv cols
__device__ __nv_bfloat16 g_Wto[(size_t)DM_ * KP];

// ---------------------------------------------------------------------------
// bf16 mma.sync GEMM: C[8192, N] = A'[8192,3072] @ B'[N,3072]^T
// CTA 128x128, 4 warps (2M x 2N), warp tile 64x64, Kc=64, 3-stage cp.async,
// 2 CTAs/SM. smem rows padded to 72 halves (144B), conflict-free (R4).
// Pipeline order: wait_group -> barrier -> load -> compute  (cp.async
// completion is per-thread; the barrier AFTER the wait is what makes other
// threads' copies visible — this was the R6 NaN bug.)
// ---------------------------------------------------------------------------
__global__ __launch_bounds__(128, 2) void gemm_mma(const __nv_bfloat16* __restrict__ A,
                                                   const __nv_bfloat16* __restrict__ Bw,
                                                   float* __restrict__ C, int ldc) {
    extern __shared__ char sm[];
    const int tid = threadIdx.x;
    const int lane = tid & 31, wid = tid >> 5;
    const int wm = wid & 1, wn = (wid >> 1) & 1;   // 2 x 2 warp grid
    const int row0 = blockIdx.y * 128;
    const int col0 = blockIdx.x * 128;

    uint32_t sb;
    asm("{ .reg .u64 t; cvta.to.shared.u64 t, %1; cvt.u32.u64 %0, t; }" : "=r"(sb) : "l"(sm));

    // stage = A(128*144 = 18432) + B(18432) = 36864 bytes; 3 stages.
    constexpr uint32_t STG = 36864u;

    float acc[4][8][4];
#pragma unroll
    for (int i = 0; i < 4; ++i)
#pragma unroll
        for (int j = 0; j < 8; ++j)
#pragma unroll
            for (int q = 0; q < 4; ++q) acc[i][j][q] = 0.f;

    auto load_chunk = [&](int c, int stg) {
        const __nv_bfloat16* gA = A + (size_t)row0 * KP + c * 64;
        uint32_t ab = sb + (uint32_t)stg * STG;
#pragma unroll
        for (int l = 0; l < 8; ++l) {
            int idx = tid + (l << 7);
            int r = idx >> 3, s = idx & 7;
            uint32_t so = ab + (uint32_t)(r * 144 + s * 16);
            const void* gp = gA + (size_t)r * KP + s * 8;
            asm volatile("cp.async.cg.shared.global [%0], [%1], 16;" :: "r"(so), "l"(gp));
        }
        const __nv_bfloat16* gB = Bw + (size_t)col0 * KP + c * 64;
        uint32_t bbx = sb + (uint32_t)stg * STG + 18432u;
#pragma unroll
        for (int l = 0; l < 8; ++l) {
            int idx = tid + (l << 7);
            int n = idx >> 3, s = idx & 7;
            uint32_t so = bbx + (uint32_t)(n * 144 + s * 16);
            const void* gp = gB + (size_t)n * KP + s * 8;
            asm volatile("cp.async.cg.shared.global [%0], [%1], 16;" :: "r"(so), "l"(gp));
        }
        asm volatile("cp.async.commit_group;" ::: "memory");
    };

    // per-lane ldmatrix base offsets (halves); pad-72 addressing from R4
    const uint32_t a_base = (uint32_t)((wm * 64 + (lane & 15)) * 72 + ((lane >> 4) << 3));
    const uint32_t b_base = (uint32_t)((wn * 64 + (((lane >> 4) & 1) << 3) + (lane & 7)) * 72 +
                                       (((lane >> 3) & 1) << 3));

    load_chunk(0, 0);
    load_chunk(1, 1);

    constexpr int NCH = KP / 64;  // 48
    for (int c = 0; c < NCH; ++c) {
        asm volatile("cp.async.wait_group 1;" ::: "memory");  // this thread's chunk c landed
        __syncthreads();   // all threads' chunk c visible; readers of stage (c-1)%3 done
        if (c + 2 < NCH)
            load_chunk(c + 2, (c + 2) % 3);
        else
            asm volatile("cp.async.commit_group;" ::: "memory");  // keep group count in step

        const uint32_t ab = sb + (uint32_t)(c % 3) * STG;
        const uint32_t bbs = ab + 18432u;
#pragma unroll
        for (int ks = 0; ks < 4; ++ks) {
            uint32_t af[4][4];
#pragma unroll
            for (int mi = 0; mi < 4; ++mi) {
                uint32_t addr = ab + (a_base + (uint32_t)(mi * 16 * 72 + ks * 16)) * 2;
                asm volatile("ldmatrix.sync.aligned.m8n8.x4.shared.b16 {%0,%1,%2,%3}, [%4];"
                             : "=r"(af[mi][0]), "=r"(af[mi][1]), "=r"(af[mi][2]), "=r"(af[mi][3])
                             : "r"(addr));
            }
            uint32_t bf[8][2];
#pragma unroll
            for (int nb = 0; nb < 4; ++nb) {
                uint32_t addr = bbs + (b_base + (uint32_t)(nb * 16 * 72 + ks * 16)) * 2;
                asm volatile("ldmatrix.sync.aligned.m8n8.x4.shared.b16 {%0,%1,%2,%3}, [%4];"
                             : "=r"(bf[2 * nb][0]), "=r"(bf[2 * nb][1]),
                               "=r"(bf[2 * nb + 1][0]), "=r"(bf[2 * nb + 1][1])
                             : "r"(addr));
            }
#pragma unroll
            for (int mi = 0; mi < 4; ++mi)
#pragma unroll
                for (int ni = 0; ni < 8; ++ni) {
                    asm volatile(
                        "mma.sync.aligned.m16n8k16.row.col.f32.bf16.bf16.f32 "
                        "{%0,%1,%2,%3}, {%4,%5,%6,%7}, {%8,%9}, {%0,%1,%2,%3};"
                        : "+f"(acc[mi][ni][0]), "+f"(acc[mi][ni][1]),
                          "+f"(acc[mi][ni][2]), "+f"(acc[mi][ni][3])
                        : "r"(af[mi][0]), "r"(af[mi][1]), "r"(af[mi][2]), "r"(af[mi][3]),
                          "r"(bf[ni][0]), "r"(bf[ni][1]));
                }
        }
    }

    const int rb = row0 + wm * 64 + (lane >> 2);
    const int cb = col0 + wn * 64 + (lane & 3) * 2;
#pragma unroll
    for (int mi = 0; mi < 4; ++mi)
#pragma unroll
        for (int ni = 0; ni < 8; ++ni) {
            int r = rb + mi * 16, cc = cb + ni * 8;
            *(float2*)(C + (size_t)r * ldc + cc) = make_float2(acc[mi][ni][0], acc[mi][ni][1]);
            *(float2*)(C + (size_t)(r + 8) * ldc + cc) =
                make_float2(acc[mi][ni][2], acc[mi][ni][3]);
        }
}

// ---------------------------------------------------------------------------
// fp32 -> 3-term split bf16: out[m] = [hi(1024) | lo(1024) | hi(1024)]
// ---------------------------------------------------------------------------
__global__ __launch_bounds__(256) void convert_split3(const float* __restrict__ in,
                                                      __nv_bfloat16* __restrict__ out) {
    size_t i = (size_t)blockIdx.x * 256 + threadIdx.x;   // float4 group id
    float4 v = ((const float4*)in)[i];
    size_t m = i >> 8;
    int k4 = (int)(i & 255) << 2;
    __nv_bfloat16 h0 = __float2bfloat16(v.x), h1 = __float2bfloat16(v.y);
    __nv_bfloat16 h2 = __float2bfloat16(v.z), h3 = __float2bfloat16(v.w);
    __nv_bfloat16 l0 = __float2bfloat16(v.x - __bfloat162float(h0));
    __nv_bfloat16 l1 = __float2bfloat16(v.y - __bfloat162float(h1));
    __nv_bfloat16 l2 = __float2bfloat16(v.z - __bfloat162float(h2));
    __nv_bfloat16 l3 = __float2bfloat16(v.w - __bfloat162float(h3));
    __nv_bfloat162 hA = __halves2bfloat162(h0, h1), hB = __halves2bfloat162(h2, h3);
    __nv_bfloat162 lA = __halves2bfloat162(l0, l1), lB = __halves2bfloat162(l2, l3);
    __nv_bfloat162* o0 = (__nv_bfloat162*)(out + m * KP + k4);
    o0[0] = hA; o0[1] = hB;
    __nv_bfloat162* o1 = (__nv_bfloat162*)(out + m * KP + 1024 + k4);
    o1[0] = lA; o1[1] = lB;
    __nv_bfloat162* o2 = (__nv_bfloat162*)(out + m * KP + 2048 + k4);
    o2[0] = hA; o2[1] = hB;
}

// W[1024][1024] fp32 -> B'[n][3072] = [hi | hi | lo]  (transposed, K-major)
__global__ __launch_bounds__(256) void transpose_split3(const float* __restrict__ W,
                                                        __nv_bfloat16* __restrict__ out) {
    __shared__ float s[32][33];
    const int tx = threadIdx.x & 31, ty = threadIdx.x >> 5;
    const int k0 = blockIdx.y << 5, n0 = blockIdx.x << 5;
#pragma unroll
    for (int r = 0; r < 32; r += 8)
        s[ty + r][tx] = W[(size_t)(k0 + ty + r) * 1024 + n0 + tx];
    __syncthreads();
#pragma unroll
    for (int r = 0; r < 32; r += 8) {
        const int n = n0 + ty + r, k = k0 + tx;
        float v = s[tx][ty + r];
        __nv_bfloat16 h = __float2bfloat16(v);
        __nv_bfloat16 l = __float2bfloat16(v - __bfloat162float(h));
        out[(size_t)n * KP + k] = h;
        out[(size_t)n * KP + 1024 + k] = h;
        out[(size_t)n * KP + 2048 + k] = l;
    }
}

// Wa/Wb [1024][16] -> Wt32[32][1024] fp32
__global__ __launch_bounds__(256) void gates_prep32(const float* __restrict__ Wa,
                                                    const float* __restrict__ Wb,
                                                    float* __restrict__ out) {
    const int o = blockIdx.x;
    const float* W = (o < 16) ? Wa : Wb;
    const int h = o & 15;
    for (int k = threadIdx.x; k < 1024; k += 256)
        out[(size_t)o * 1024 + k] = W[k * 16 + h];
}

// ---------------------------------------------------------------------------
// Gates: logits = x @ Wt32^T, + bias, sigmoid. Block = 64 rows x 32 outputs.
// ---------------------------------------------------------------------------
__global__ __launch_bounds__(256) void gates64(const float* __restrict__ x,
                                               const float* __restrict__ Wt,
                                               const float* __restrict__ ba,
                                               const float* __restrict__ bb,
                                               float* __restrict__ alpha,
                                               float* __restrict__ beta) {
    __shared__ float xs[64][64];
    __shared__ float ws[32][65];
    const int tid = threadIdx.x;
    const int row0 = blockIdx.x * 64;
    const int rg = tid >> 5;
    const int o = tid & 31;

    float acc[8];
#pragma unroll
    for (int p = 0; p < 8; ++p) acc[p] = 0.f;

    for (int kc = 0; kc < 16; ++kc) {
        __syncthreads();
#pragma unroll
        for (int l = 0; l < 4; ++l) {
            int idx = tid + (l << 8);
            int r = idx >> 4, q = idx & 15;
            float4 v = *(const float4*)(x + (size_t)(row0 + r) * 1024 + kc * 64 + q * 4);
            *(float4*)(&xs[r][q * 4]) = v;
        }
#pragma unroll
        for (int l = 0; l < 2; ++l) {
            int idx = tid + (l << 8);
            int r = idx >> 4, q = idx & 15;
            float4 v = *(const float4*)(Wt + (size_t)r * 1024 + kc * 64 + q * 4);
            ws[r][q * 4 + 0] = v.x; ws[r][q * 4 + 1] = v.y;
            ws[r][q * 4 + 2] = v.z; ws[r][q * 4 + 3] = v.w;
        }
        __syncthreads();
#pragma unroll 8
        for (int k = 0; k < 64; ++k) {
            float wv = ws[o][k];
#pragma unroll
            for (int p = 0; p < 8; ++p)
                acc[p] = fmaf(xs[rg * 8 + p][k], wv, acc[p]);
        }
    }

    const float bias = (o < 16) ? ba[o] : bb[o - 16];
#pragma unroll
    for (int p = 0; p < 8; ++p) {
        float r = 1.f / (1.f + expf(-(acc[p] + bias)));
        int row = row0 + rg * 8 + p;
        if (o < 16) alpha[(size_t)row * 16 + o] = r;
        else        beta[(size_t)row * 16 + (o - 16)] = r;
    }
}

// ---------------------------------------------------------------------------
// K normalize over fused QKV buffer (K = cols [1024,2048))
// ---------------------------------------------------------------------------
__global__ __launch_bounds__(256) void knorm2(float* __restrict__ QKV) {
    const int w = (int)((blockIdx.x * blockDim.x + threadIdx.x) >> 5);
    const int lane = threadIdx.x & 31;
    if (w >= NROWS * H_) return;
    const int n = w >> 4, h = w & 15;
    float2* p = (float2*)(QKV + (size_t)n * 3072 + 1024 + h * 64);
    float2 v = p[lane];
    float ss = v.x * v.x + v.y * v.y;
#pragma unroll
    for (int m = 16; m; m >>= 1) ss += __shfl_xor_sync(~0u, ss, m);
    float inv = 1.f / fmaxf(sqrtf(ss), 1e-12f);
    v.x *= inv; v.y *= inv;
    p[lane] = v;
}

// ---------------------------------------------------------------------------
// Sequential scan: 128 blocks (one per (b,h,row-half)), 128 threads.
// ---------------------------------------------------------------------------
__global__ __launch_bounds__(128) void scan_kernel2(
    const float* __restrict__ QKV, const float* __restrict__ alpha,
    const float* __restrict__ beta, const float* __restrict__ S0,
    float* __restrict__ Y, float* __restrict__ Sout) {
    constexpr int CH = 16;
    __shared__ float cq[2][CH][64];
    __shared__ float ck[2][CH][64];
    __shared__ float cv[2][CH][32];
    __shared__ float ca[2][CH];
    __shared__ float cb[2][CH];

    const int tid = threadIdx.x;
    const int bh2 = blockIdx.x;          // 0..127
    const int bh = bh2 >> 1, half = bh2 & 1;
    const int b = bh >> 4, h = bh & 15;
    const int i = tid >> 2;              // row 0..31
    const int gi = half * 32 + i;        // row 0..63
    const int jg = tid & 3;
    const int j0 = jg << 4;

    float4 s4[4];
    {
        const float4* sp = (const float4*)(S0 + ((size_t)bh * 64 + gi) * 64 + j0);
        s4[0] = sp[0]; s4[1] = sp[1]; s4[2] = sp[2]; s4[3] = sp[3];
    }

    const float* rowQ = QKV + (size_t)b * T_ * 3072 + (size_t)h * 64;

    auto load_chunk = [&](int t0, int buf) {
#pragma unroll
        for (int l = 0; l < 2; ++l) {
            int idx = tid + (l << 7);
            int st = idx >> 4, f = (idx & 15) << 2;
            const float* base = rowQ + (size_t)(t0 + st) * 3072;
            *(float4*)(&cq[buf][st][f]) = *(const float4*)(base + f);
            *(float4*)(&ck[buf][st][f]) = *(const float4*)(base + 1024 + f);
        }
        {
            int st = tid >> 3, f = (tid & 7) << 2;
            const float* base = rowQ + (size_t)(t0 + st) * 3072 + 2048 + half * 32;
            *(float4*)(&cv[buf][st][f]) = *(const float4*)(base + f);
        }
        if (tid < CH)
            ca[buf][tid] = alpha[((size_t)b * T_ + t0 + tid) * H_ + h];
        else if (tid < 2 * CH)
            cb[buf][tid - CH] = beta[((size_t)b * T_ + t0 + tid - CH) * H_ + h];
    };

    const size_t ybase = (size_t)b * T_ * DM_ + (size_t)h * 64 + gi;
    const int nch = T_ / CH;
    load_chunk(0, 0);
    __syncthreads();

    for (int c = 0; c < nch; ++c) {
        const int buf = c & 1;
        if (c + 1 < nch) load_chunk((c + 1) * CH, buf ^ 1);

#pragma unroll 4
        for (int s = 0; s < CH; ++s) {
            const float a = ca[buf][s];
            const float bg = cb[buf][s];
            const float bv = bg * cv[buf][s][i];
            const float4* kp = (const float4*)(&ck[buf][s][j0]);
            const float4* qp = (const float4*)(&cq[buf][s][j0]);
            float partial = 0.f;
#pragma unroll
            for (int v = 0; v < 4; ++v) {
                float4 kk = kp[v];
                float4 qq = qp[v];
                s4[v].x = fmaf(a, s4[v].x, bv * kk.x); partial = fmaf(s4[v].x, qq.x, partial);
                s4[v].y = fmaf(a, s4[v].y, bv * kk.y); partial = fmaf(s4[v].y, qq.y, partial);
                s4[v].z = fmaf(a, s4[v].z, bv * kk.z); partial = fmaf(s4[v].z, qq.z, partial);
                s4[v].w = fmaf(a, s4[v].w, bv * kk.w); partial = fmaf(s4[v].w, qq.w, partial);
            }
            partial += __shfl_xor_sync(~0u, partial, 1);
            partial += __shfl_xor_sync(~0u, partial, 2);
            if (jg == 0)
                Y[ybase + (size_t)(c * CH + s) * DM_] = partial;
        }
        __syncthreads();
    }

    float4* so = (float4*)(Sout + ((size_t)bh * 64 + gi) * 64 + j0);
    so[0] = s4[0]; so[1] = s4[1]; so[2] = s4[2]; so[3] = s4[3];
}

// ---------------------------------------------------------------------------
extern "C" void kernel_launch(void* const* d_in, const int* in_sizes, int n_in,
                              void* d_out, int out_size) {
    (void)in_sizes; (void)n_in;
    const float* x  = (const float*)d_in[0];
    const float* S0 = (const float*)d_in[1];
    const float* Wq = (const float*)d_in[2];
    const float* Wk = (const float*)d_in[3];
    const float* Wv = (const float*)d_in[4];
    const float* Wa = (const float*)d_in[5];
    const float* ba = (const float*)d_in[6];
    const float* Wb = (const float*)d_in[7];
    const float* bb = (const float*)d_in[8];
    const float* Wo = (const float*)d_in[9];
    float* out = (float*)d_out;

    float *QKVd, *Yd, *al, *be, *Sdump, *Wab32;
    __nv_bfloat16 *A2, *Y2, *Wqkv, *Wto;
    cudaGetSymbolAddress((void**)&QKVd, g_QKV);
    cudaGetSymbolAddress((void**)&Yd, g_Y);
    cudaGetSymbolAddress((void**)&al, g_alpha);
    cudaGetSymbolAddress((void**)&be, g_beta);
    cudaGetSymbolAddress((void**)&Sdump, g_Sdump);
    cudaGetSymbolAddress((void**)&Wab32, g_Wab32);
    cudaGetSymbolAddress((void**)&A2, g_A2);
    cudaGetSymbolAddress((void**)&Y2, g_Y2);
    cudaGetSymbolAddress((void**)&Wqkv, g_Wqkv);
    cudaGetSymbolAddress((void**)&Wto, g_Wto);

    float* Sout = (out_size >= NROWS * DM_ + STATE_ELEMS) ? out + (size_t)NROWS * DM_ : Sdump;

    constexpr int GSMEM = 3 * 36864;   // 110592 per CTA (3-stage)
    cudaFuncSetAttribute(gemm_mma, cudaFuncAttributeMaxDynamicSharedMemorySize, GSMEM);

    convert_split3<<<NROWS, 256>>>(x, A2);
    transpose_split3<<<dim3(32, 32), 256>>>(Wq, Wqkv);
    transpose_split3<<<dim3(32, 32), 256>>>(Wk, Wqkv + (size_t)1024 * KP);
    transpose_split3<<<dim3(32, 32), 256>>>(Wv, Wqkv + (size_t)2048 * KP);
    gates_prep32<<<32, 256>>>(Wa, Wb, Wab32);
    gemm_mma<<<dim3(3072 / 128, NROWS / 128), 128, GSMEM>>>(A2, Wqkv, QKVd, 3072);
    gates64<<<NROWS / 64, 256>>>(x, Wab32, ba, bb, al, be);
    knorm2<<<(NROWS * H_ * 32) / 256, 256>>>(QKVd);
    scan_kernel2<<<128, 128>>>(QKVd, al, be, S0, Yd, Sout);
    convert_split3<<<NROWS, 256>>>(Yd, Y2);
    transpose_split3<<<dim3(32, 32), 256>>>(Wo, Wto);
    gemm_mma<<<dim3(1024 / 128, NROWS / 128), 128, GSMEM>>>(Y2, Wto, out, 1024);
}